// round 4
// baseline (speedup 1.0000x reference)
#include <cuda_runtime.h>

#define NJ 21
#define HD 42
#define HID 64
#define TOK_PER_BLK 32
#define BN_EPS 1e-5f

// Compile-time hand-graph neighbor lists (incl. self). Values come from the
// adj input at runtime; only the sparsity pattern is hardcoded (it is fixed
// by construction in the reference's hand_adjacency()).
__device__ constexpr int NBR_CNT[NJ] = {6,3,3,3,2, 3,3,3,2, 3,3,3,2, 3,3,3,2, 3,3,3,2};
__device__ constexpr int NBRS[NJ][6] = {
    {0,1,5,9,13,17},
    {0,1,2,0,0,0}, {1,2,3,0,0,0}, {2,3,4,0,0,0}, {3,4,0,0,0,0},
    {0,5,6,0,0,0}, {5,6,7,0,0,0}, {6,7,8,0,0,0}, {7,8,0,0,0,0},
    {0,9,10,0,0,0}, {9,10,11,0,0,0}, {10,11,12,0,0,0}, {11,12,0,0,0,0},
    {0,13,14,0,0,0}, {13,14,15,0,0,0}, {14,15,16,0,0,0}, {15,16,0,0,0,0},
    {0,17,18,0,0,0}, {17,18,19,0,0,0}, {18,19,20,0,0,0}, {19,20,0,0,0,0},
};

__global__ void __launch_bounds__(TOK_PER_BLK)
hand_gcn_kernel(const float* __restrict__ x,
                const float* __restrict__ adj,
                const float* __restrict__ W1, const float* __restrict__ b1,
                const float* __restrict__ W2, const float* __restrict__ b2,
                const float* __restrict__ g1, const float* __restrict__ be1,
                const float* __restrict__ m1, const float* __restrict__ v1,
                const float* __restrict__ g2, const float* __restrict__ be2,
                const float* __restrict__ m2, const float* __restrict__ v2,
                float* __restrict__ out)
{
    __shared__ float  s_adj[NJ * NJ];
    __shared__ float4 s_wp[HID];          // {W1'[0][d], W1'[1][d], b1'[d], W2'[d][0]}
    __shared__ float  s_w2b[HID];         // W2'[d][1]
    __shared__ float  s_b2[2];
    __shared__ float  s_x[TOK_PER_BLK * HD];

    const int tid = threadIdx.x;

    // ---- fold BN into weights (tiny, recomputed per block) ----
    {
        const float sc2a = g2[0] * rsqrtf(v2[0] + BN_EPS);
        const float sc2b = g2[1] * rsqrtf(v2[1] + BN_EPS);
        for (int d = tid; d < HID; d += TOK_PER_BLK) {
            float sc1 = g1[d] * rsqrtf(v1[d] + BN_EPS);
            float w0  = W1[d]        * sc1;   // W1[0][d]
            float w1  = W1[HID + d]  * sc1;   // W1[1][d]
            float bb  = (b1[d] - m1[d]) * sc1 + be1[d];
            float w2a = W2[d * 2 + 0] * sc2a;
            float w2b = W2[d * 2 + 1] * sc2b;
            s_wp[d]  = make_float4(w0, w1, bb, w2a);
            s_w2b[d] = w2b;
        }
        if (tid < 2) {
            float sc2 = g2[tid] * rsqrtf(v2[tid] + BN_EPS);
            s_b2[tid] = (b2[tid] - m2[tid]) * sc2 + be2[tid];
        }
    }
    for (int i = tid; i < NJ * NJ; i += TOK_PER_BLK) s_adj[i] = adj[i];

    // ---- stage this block's 32 token rows (coalesced SCALAR loads:
    //      no alignment assumption on the global pointer) ----
    const int base = blockIdx.x * (TOK_PER_BLK * HD);
    #pragma unroll
    for (int i = tid; i < TOK_PER_BLK * HD; i += TOK_PER_BLK) s_x[i] = x[base + i];
    __syncthreads();

    // ---- per-thread token ----
    float xr0[NJ], xr1[NJ];
    {
        const float* row = s_x + tid * HD;   // 168B row stride: float2-safe in smem
        #pragma unroll
        for (int j = 0; j < NJ; ++j) {
            float2 v = *reinterpret_cast<const float2*>(row + 2 * j);
            xr0[j] = v.x; xr1[j] = v.y;
        }
    }

    // agg1 = adj @ xr   (sparse)
    float a0[NJ], a1[NJ];
    #pragma unroll
    for (int i = 0; i < NJ; ++i) {
        float s0 = 0.f, s1 = 0.f;
        #pragma unroll
        for (int k = 0; k < 6; ++k) {
            if (k < NBR_CNT[i]) {
                const int n = NBRS[i][k];
                const float v = s_adj[i * NJ + n];
                s0 = fmaf(v, xr0[n], s0);
                s1 = fmaf(v, xr1[n], s1);
            }
        }
        a0[i] = s0; a1[i] = s1;
    }

    // fused MLP: t[j][:] = relu(a[j]@W1' + b1') @ W2'
    float acc0[NJ], acc1[NJ];
    #pragma unroll
    for (int j = 0; j < NJ; ++j) { acc0[j] = 0.f; acc1[j] = 0.f; }

    #pragma unroll 4
    for (int d = 0; d < HID; ++d) {
        const float4 wp = s_wp[d];
        const float w2b = s_w2b[d];
        #pragma unroll
        for (int j = 0; j < NJ; ++j) {
            float h = fmaf(wp.y, a1[j], fmaf(wp.x, a0[j], wp.z));
            h = fmaxf(h, 0.f);
            acc0[j] = fmaf(h, wp.w, acc0[j]);
            acc1[j] = fmaf(h, w2b, acc1[j]);
        }
    }

    // agg2 = adj @ t  (sparse), + b2' + residual; write back to own smem row
    {
        const float bo0 = s_b2[0], bo1 = s_b2[1];
        float* row = s_x + tid * HD;
        #pragma unroll
        for (int i = 0; i < NJ; ++i) {
            float s0 = 0.f, s1 = 0.f;
            #pragma unroll
            for (int k = 0; k < 6; ++k) {
                if (k < NBR_CNT[i]) {
                    const int n = NBRS[i][k];
                    const float v = s_adj[i * NJ + n];
                    s0 = fmaf(v, acc0[n], s0);
                    s1 = fmaf(v, acc1[n], s1);
                }
            }
            float2 o;
            o.x = s0 + bo0 + xr0[i];
            o.y = s1 + bo1 + xr1[i];
            *reinterpret_cast<float2*>(row + 2 * i) = o;
        }
    }
    __syncthreads();

    // ---- coalesced SCALAR writeback ----
    #pragma unroll
    for (int i = tid; i < TOK_PER_BLK * HD; i += TOK_PER_BLK) out[base + i] = s_x[i];
}

extern "C" void kernel_launch(void* const* d_in, const int* in_sizes, int n_in,
                              void* d_out, int out_size)
{
    const float* x   = (const float*)d_in[0];
    const float* adj = (const float*)d_in[1];
    const float* W1  = (const float*)d_in[2];
    const float* b1  = (const float*)d_in[3];
    const float* W2  = (const float*)d_in[4];
    const float* b2  = (const float*)d_in[5];
    const float* g1  = (const float*)d_in[6];
    const float* be1 = (const float*)d_in[7];
    const float* m1  = (const float*)d_in[8];
    const float* v1  = (const float*)d_in[9];
    const float* g2  = (const float*)d_in[10];
    const float* be2 = (const float*)d_in[11];
    const float* m2  = (const float*)d_in[12];
    const float* v2  = (const float*)d_in[13];
    float* out = (float*)d_out;

    const int n_tok = in_sizes[0] / HD;          // 32768
    const int blocks = n_tok / TOK_PER_BLK;      // 1024

    hand_gcn_kernel<<<blocks, TOK_PER_BLK>>>(
        x, adj, W1, b1, W2, b2, g1, be1, m1, v1, g2, be2, m2, v2, out);
}

// round 5
// speedup vs baseline: 1.1212x; 1.1212x over previous
#include <cuda_runtime.h>

#define NJ 21
#define HD 42
#define HID 64
#define TOKENS_PER_BLK 64
#define THREADS 128
#define XROW 43   // padded s_x row stride (gcd(43,32)=1 -> conflict-free)
#define TROW 45   // padded s_t row stride (gcd(45,32)=1 -> conflict-free)
#define BN_EPS 1e-5f

// Compile-time hand-graph neighbor lists (incl. self). Values come from the
// adj input at runtime; only the sparsity pattern is hardcoded (fixed by
// construction in the reference's hand_adjacency()).
__device__ constexpr int NBR_CNT[NJ] = {6,3,3,3,2, 3,3,3,2, 3,3,3,2, 3,3,3,2, 3,3,3,2};
__device__ constexpr int NBRS[NJ][6] = {
    {0,1,5,9,13,17},
    {0,1,2,0,0,0}, {1,2,3,0,0,0}, {2,3,4,0,0,0}, {3,4,0,0,0,0},
    {0,5,6,0,0,0}, {5,6,7,0,0,0}, {6,7,8,0,0,0}, {7,8,0,0,0,0},
    {0,9,10,0,0,0}, {9,10,11,0,0,0}, {10,11,12,0,0,0}, {11,12,0,0,0,0},
    {0,13,14,0,0,0}, {13,14,15,0,0,0}, {14,15,16,0,0,0}, {15,16,0,0,0,0},
    {0,17,18,0,0,0}, {17,18,19,0,0,0}, {18,19,20,0,0,0}, {19,20,0,0,0,0},
};

// Phase A: agg1 (from s_x) + fused folded MLP; deposit t into s_t.
template<int J0, int NJL>
__device__ __forceinline__ void phaseA(
    int tok, const float* __restrict__ s_x, float* __restrict__ s_t,
    const float* __restrict__ s_adj, const float4* __restrict__ s_wp,
    const float* __restrict__ s_w2b)
{
    const float* xrow = s_x + tok * XROW;

    float a0[NJL], a1[NJL];
    #pragma unroll
    for (int l = 0; l < NJL; ++l) {
        const int i = J0 + l;
        float s0 = 0.f, s1 = 0.f;
        #pragma unroll
        for (int k = 0; k < 6; ++k) {
            if (k < NBR_CNT[i]) {
                const int n = NBRS[i][k];
                const float v = s_adj[i * NJ + n];
                s0 = fmaf(v, xrow[2 * n],     s0);
                s1 = fmaf(v, xrow[2 * n + 1], s1);
            }
        }
        a0[l] = s0; a1[l] = s1;
    }

    float acc0[NJL], acc1[NJL];
    #pragma unroll
    for (int l = 0; l < NJL; ++l) { acc0[l] = 0.f; acc1[l] = 0.f; }

    #pragma unroll 4
    for (int d = 0; d < HID; ++d) {
        const float4 wp = s_wp[d];     // {W1'[0][d], W1'[1][d], b1'[d], W2'[d][0]}
        const float w2b = s_w2b[d];    // W2'[d][1]
        #pragma unroll
        for (int l = 0; l < NJL; ++l) {
            float h = fmaf(wp.y, a1[l], fmaf(wp.x, a0[l], wp.z));
            h = fmaxf(h, 0.f);
            acc0[l] = fmaf(h, wp.w, acc0[l]);
            acc1[l] = fmaf(h, w2b,  acc1[l]);
        }
    }

    float* trow = s_t + tok * TROW;
    #pragma unroll
    for (int l = 0; l < NJL; ++l) {
        trow[(J0 + l) * 2]     = acc0[l];
        trow[(J0 + l) * 2 + 1] = acc1[l];
    }
}

// Phase B: agg2 (from s_t) + folded bias + residual; result overwrites own
// joints' slots in s_x (each slot written only by its owner).
template<int J0, int NJL>
__device__ __forceinline__ void phaseB(
    int tok, float* __restrict__ s_x, const float* __restrict__ s_t,
    const float* __restrict__ s_adj, float b2a, float b2b)
{
    const float* trow = s_t + tok * TROW;
    float* xrow = s_x + tok * XROW;
    #pragma unroll
    for (int l = 0; l < NJL; ++l) {
        const int i = J0 + l;
        float s0 = 0.f, s1 = 0.f;
        #pragma unroll
        for (int k = 0; k < 6; ++k) {
            if (k < NBR_CNT[i]) {
                const int n = NBRS[i][k];
                const float v = s_adj[i * NJ + n];
                s0 = fmaf(v, trow[2 * n],     s0);
                s1 = fmaf(v, trow[2 * n + 1], s1);
            }
        }
        xrow[2 * i]     = s0 + b2a + xrow[2 * i];
        xrow[2 * i + 1] = s1 + b2b + xrow[2 * i + 1];
    }
}

__global__ void __launch_bounds__(THREADS)
hand_gcn_kernel(const float* __restrict__ x,
                const float* __restrict__ adj,
                const float* __restrict__ W1, const float* __restrict__ b1,
                const float* __restrict__ W2, const float* __restrict__ b2,
                const float* __restrict__ g1, const float* __restrict__ be1,
                const float* __restrict__ m1, const float* __restrict__ v1,
                const float* __restrict__ g2, const float* __restrict__ be2,
                const float* __restrict__ m2, const float* __restrict__ v2,
                float* __restrict__ out)
{
    __shared__ float  s_adj[NJ * NJ];
    __shared__ float4 s_wp[HID];
    __shared__ float  s_w2b[HID];
    __shared__ float  s_b2[2];
    __shared__ float  s_x[TOKENS_PER_BLK * XROW];
    __shared__ float  s_t[TOKENS_PER_BLK * TROW];

    const int tid = threadIdx.x;

    // ---- fold BN into weights (one d per thread) ----
    if (tid < HID) {
        const int d = tid;
        float sc1 = g1[d] * rsqrtf(v1[d] + BN_EPS);
        float sc2a = g2[0] * rsqrtf(v2[0] + BN_EPS);
        float sc2b = g2[1] * rsqrtf(v2[1] + BN_EPS);
        float w0  = W1[d]       * sc1;
        float w1  = W1[HID + d] * sc1;
        float bb  = (b1[d] - m1[d]) * sc1 + be1[d];
        s_wp[d]   = make_float4(w0, w1, bb, W2[d * 2] * sc2a);
        s_w2b[d]  = W2[d * 2 + 1] * sc2b;
    } else if (tid < HID + 2) {
        const int c = tid - HID;
        float sc2 = g2[c] * rsqrtf(v2[c] + BN_EPS);
        s_b2[c] = (b2[c] - m2[c]) * sc2 + be2[c];
    }
    for (int i = tid; i < NJ * NJ; i += THREADS) s_adj[i] = adj[i];

    // ---- stage input, coalesced scalar (no global alignment assumption) ----
    const int base = blockIdx.x * (TOKENS_PER_BLK * HD);
    #pragma unroll
    for (int i = tid; i < TOKENS_PER_BLK * HD; i += THREADS) {
        const int r = i / HD, c = i - r * HD;
        s_x[r * XROW + c] = x[base + i];
    }
    __syncthreads();

    // warp-uniform half assignment: warp w -> tokens (w/2)*32+lane, half w&1
    const int wid  = tid >> 5;
    const int lane = tid & 31;
    const int tok  = ((wid >> 1) << 5) + lane;
    const int half = wid & 1;

    if (half == 0) phaseA<0, 11>(tok, s_x, s_t, s_adj, s_wp, s_w2b);
    else           phaseA<11, 10>(tok, s_x, s_t, s_adj, s_wp, s_w2b);
    __syncthreads();

    const float b2a = s_b2[0], b2b = s_b2[1];
    if (half == 0) phaseB<0, 11>(tok, s_x, s_t, s_adj, b2a, b2b);
    else           phaseB<11, 10>(tok, s_x, s_t, s_adj, b2a, b2b);
    __syncthreads();

    // ---- coalesced scalar writeback ----
    #pragma unroll
    for (int i = tid; i < TOKENS_PER_BLK * HD; i += THREADS) {
        const int r = i / HD, c = i - r * HD;
        out[base + i] = s_x[r * XROW + c];
    }
}

extern "C" void kernel_launch(void* const* d_in, const int* in_sizes, int n_in,
                              void* d_out, int out_size)
{
    const float* x   = (const float*)d_in[0];
    const float* adj = (const float*)d_in[1];
    const float* W1  = (const float*)d_in[2];
    const float* b1  = (const float*)d_in[3];
    const float* W2  = (const float*)d_in[4];
    const float* b2  = (const float*)d_in[5];
    const float* g1  = (const float*)d_in[6];
    const float* be1 = (const float*)d_in[7];
    const float* m1  = (const float*)d_in[8];
    const float* v1  = (const float*)d_in[9];
    const float* g2  = (const float*)d_in[10];
    const float* be2 = (const float*)d_in[11];
    const float* m2  = (const float*)d_in[12];
    const float* v2  = (const float*)d_in[13];
    float* out = (float*)d_out;

    const int n_tok  = in_sizes[0] / HD;            // 32768
    const int blocks = n_tok / TOKENS_PER_BLK;      // 512

    hand_gcn_kernel<<<blocks, THREADS>>>(
        x, adj, W1, b1, W2, b2, g1, be1, m1, v1, g2, be2, m2, v2, out);
}

// round 6
// speedup vs baseline: 1.2542x; 1.1186x over previous
#include <cuda_runtime.h>

#define NJ 21
#define HD 42
#define HID 64
#define TOKENS_PER_BLK 32
#define THREADS 128
#define XROW 43   // padded s_x row stride in floats (gcd(43,32)=1 -> conflict-free)
#define TROW 45   // padded s_t row stride (gcd(45,32)=1 -> conflict-free)
#define BN_EPS 1e-5f

typedef unsigned long long u64;

// Compile-time hand-graph neighbor lists (incl. self). Values come from the
// adj input at runtime; only the sparsity pattern is hardcoded (fixed by
// construction in the reference's hand_adjacency()).
__device__ constexpr int NBR_CNT[NJ] = {6,3,3,3,2, 3,3,3,2, 3,3,3,2, 3,3,3,2, 3,3,3,2};
__device__ constexpr int NBRS[NJ][6] = {
    {0,1,5,9,13,17},
    {0,1,2,0,0,0}, {1,2,3,0,0,0}, {2,3,4,0,0,0}, {3,4,0,0,0,0},
    {0,5,6,0,0,0}, {5,6,7,0,0,0}, {6,7,8,0,0,0}, {7,8,0,0,0,0},
    {0,9,10,0,0,0}, {9,10,11,0,0,0}, {10,11,12,0,0,0}, {11,12,0,0,0,0},
    {0,13,14,0,0,0}, {13,14,15,0,0,0}, {14,15,16,0,0,0}, {15,16,0,0,0,0},
    {0,17,18,0,0,0}, {17,18,19,0,0,0}, {18,19,20,0,0,0}, {19,20,0,0,0,0},
};

__device__ __forceinline__ u64 pack2(float lo, float hi) {
    u64 r; asm("mov.b64 %0, {%1, %2};" : "=l"(r) : "f"(lo), "f"(hi)); return r;
}
__device__ __forceinline__ void unpack2(u64 v, float& lo, float& hi) {
    asm("mov.b64 {%0, %1}, %2;" : "=f"(lo), "=f"(hi) : "l"(v));
}
__device__ __forceinline__ u64 fma2(u64 a, u64 b, u64 c) {
    u64 d; asm("fma.rn.f32x2 %0, %1, %2, %3;" : "=l"(d) : "l"(a), "l"(b), "l"(c)); return d;
}

// Phase A: agg1 (from s_x) + fused folded MLP (f32x2-packed over d pairs);
// deposit t into s_t.
template<int J0, int NJL>
__device__ __forceinline__ void phaseA(
    int tok, const float* __restrict__ s_x, float* __restrict__ s_t,
    const float* __restrict__ s_adj,
    const float* __restrict__ s_wA,   // [dp]: {wx_e, wx_o, wy_e, wy_o}
    const float* __restrict__ s_wB,   // [dp]: {wb_e, wb_o, w2a_e, w2a_o}
    const float* __restrict__ s_wC)   // [dp]: {w2b_e, w2b_o}
{
    const float* xrow = s_x + tok * XROW;

    // sparse agg1 (scalar; small fraction of work)
    float a0[NJL], a1[NJL];
    #pragma unroll
    for (int l = 0; l < NJL; ++l) {
        const int i = J0 + l;
        float s0 = 0.f, s1 = 0.f;
        #pragma unroll
        for (int k = 0; k < 6; ++k) {
            if (k < NBR_CNT[i]) {
                const int n = NBRS[i][k];
                const float v = s_adj[i * NJ + n];
                s0 = fmaf(v, xrow[2 * n],     s0);
                s1 = fmaf(v, xrow[2 * n + 1], s1);
            }
        }
        a0[l] = s0; a1[l] = s1;
    }

    // broadcast-pack activations once
    u64 A0[NJL], A1[NJL], ACC0[NJL], ACC1[NJL];
    #pragma unroll
    for (int l = 0; l < NJL; ++l) {
        A0[l] = pack2(a0[l], a0[l]);
        A1[l] = pack2(a1[l], a1[l]);
        ACC0[l] = 0ull; ACC1[l] = 0ull;
    }

    const ulonglong2* WA = reinterpret_cast<const ulonglong2*>(s_wA);
    const ulonglong2* WB = reinterpret_cast<const ulonglong2*>(s_wB);
    const u64*        WC = reinterpret_cast<const u64*>(s_wC);

    #pragma unroll 4
    for (int dp = 0; dp < HID / 2; ++dp) {
        const ulonglong2 va = WA[dp];   // .x = wx2, .y = wy2
        const ulonglong2 vb = WB[dp];   // .x = wb2, .y = w2a2
        const u64        vc = WC[dp];   //      w2b2
        #pragma unroll
        for (int l = 0; l < NJL; ++l) {
            u64 h2 = fma2(va.x, A0[l], fma2(va.y, A1[l], vb.x));
            float hl, hh; unpack2(h2, hl, hh);
            hl = fmaxf(hl, 0.f); hh = fmaxf(hh, 0.f);
            h2 = pack2(hl, hh);
            ACC0[l] = fma2(h2, vb.y, ACC0[l]);
            ACC1[l] = fma2(h2, vc,   ACC1[l]);
        }
    }

    float* trow = s_t + tok * TROW;
    #pragma unroll
    for (int l = 0; l < NJL; ++l) {
        float lo, hi;
        unpack2(ACC0[l], lo, hi); trow[(J0 + l) * 2]     = lo + hi;
        unpack2(ACC1[l], lo, hi); trow[(J0 + l) * 2 + 1] = lo + hi;
    }
}

// Phase B: agg2 (from s_t) + folded bias + residual; overwrite own joints in s_x.
template<int J0, int NJL>
__device__ __forceinline__ void phaseB(
    int tok, float* __restrict__ s_x, const float* __restrict__ s_t,
    const float* __restrict__ s_adj, float b2a, float b2b)
{
    const float* trow = s_t + tok * TROW;
    float* xrow = s_x + tok * XROW;
    #pragma unroll
    for (int l = 0; l < NJL; ++l) {
        const int i = J0 + l;
        float s0 = 0.f, s1 = 0.f;
        #pragma unroll
        for (int k = 0; k < 6; ++k) {
            if (k < NBR_CNT[i]) {
                const int n = NBRS[i][k];
                const float v = s_adj[i * NJ + n];
                s0 = fmaf(v, trow[2 * n],     s0);
                s1 = fmaf(v, trow[2 * n + 1], s1);
            }
        }
        xrow[2 * i]     = s0 + b2a + xrow[2 * i];
        xrow[2 * i + 1] = s1 + b2b + xrow[2 * i + 1];
    }
}

__global__ void __launch_bounds__(THREADS)
hand_gcn_kernel(const float* __restrict__ x,
                const float* __restrict__ adj,
                const float* __restrict__ W1, const float* __restrict__ b1,
                const float* __restrict__ W2, const float* __restrict__ b2,
                const float* __restrict__ g1, const float* __restrict__ be1,
                const float* __restrict__ m1, const float* __restrict__ v1,
                const float* __restrict__ g2, const float* __restrict__ be2,
                const float* __restrict__ m2, const float* __restrict__ v2,
                float* __restrict__ out)
{
    __shared__ float  s_adj[NJ * NJ];
    __shared__ __align__(16) float s_wA[HID * 2];   // {wx_e,wx_o,wy_e,wy_o} per dp
    __shared__ __align__(16) float s_wB[HID * 2];   // {wb_e,wb_o,w2a_e,w2a_o} per dp
    __shared__ __align__(16) float s_wC[HID];       // {w2b_e,w2b_o} per dp
    __shared__ float  s_b2[2];
    __shared__ float  s_x[TOKENS_PER_BLK * XROW];
    __shared__ float  s_t[TOKENS_PER_BLK * TROW];

    const int tid = threadIdx.x;

    // ---- fold BN into weights; scatter into d-pair-packed layout ----
    if (tid < HID) {
        const int d = tid, dp = d >> 1, par = d & 1;
        const float sc1  = g1[d] * rsqrtf(v1[d] + BN_EPS);
        const float sc2a = g2[0] * rsqrtf(v2[0] + BN_EPS);
        const float sc2b = g2[1] * rsqrtf(v2[1] + BN_EPS);
        s_wA[dp * 4 + par]     = W1[d]       * sc1;              // wx
        s_wA[dp * 4 + 2 + par] = W1[HID + d] * sc1;              // wy
        s_wB[dp * 4 + par]     = (b1[d] - m1[d]) * sc1 + be1[d]; // wb
        s_wB[dp * 4 + 2 + par] = W2[d * 2]     * sc2a;           // w2a
        s_wC[dp * 2 + par]     = W2[d * 2 + 1] * sc2b;           // w2b
    } else if (tid < HID + 2) {
        const int c = tid - HID;
        const float sc2 = g2[c] * rsqrtf(v2[c] + BN_EPS);
        s_b2[c] = (b2[c] - m2[c]) * sc2 + be2[c];
    }
    for (int i = tid; i < NJ * NJ; i += THREADS) s_adj[i] = adj[i];

    // ---- stage input, coalesced scalar (no global alignment assumption) ----
    const int base = blockIdx.x * (TOKENS_PER_BLK * HD);
    #pragma unroll
    for (int i = tid; i < TOKENS_PER_BLK * HD; i += THREADS) {
        const int r = i / HD, c = i - r * HD;
        s_x[r * XROW + c] = x[base + i];
    }
    __syncthreads();

    // warp-uniform quarter assignment: warp w handles joint-quarter w of token=lane
    const int q    = tid >> 5;
    const int tok  = tid & 31;

    if      (q == 0) phaseA<0,  6>(tok, s_x, s_t, s_adj, s_wA, s_wB, s_wC);
    else if (q == 1) phaseA<6,  5>(tok, s_x, s_t, s_adj, s_wA, s_wB, s_wC);
    else if (q == 2) phaseA<11, 5>(tok, s_x, s_t, s_adj, s_wA, s_wB, s_wC);
    else             phaseA<16, 5>(tok, s_x, s_t, s_adj, s_wA, s_wB, s_wC);
    __syncthreads();

    const float b2a = s_b2[0], b2b = s_b2[1];
    if      (q == 0) phaseB<0,  6>(tok, s_x, s_t, s_adj, b2a, b2b);
    else if (q == 1) phaseB<6,  5>(tok, s_x, s_t, s_adj, b2a, b2b);
    else if (q == 2) phaseB<11, 5>(tok, s_x, s_t, s_adj, b2a, b2b);
    else             phaseB<16, 5>(tok, s_x, s_t, s_adj, b2a, b2b);
    __syncthreads();

    // ---- coalesced scalar writeback ----
    #pragma unroll
    for (int i = tid; i < TOKENS_PER_BLK * HD; i += THREADS) {
        const int r = i / HD, c = i - r * HD;
        out[base + i] = s_x[r * XROW + c];
    }
}

extern "C" void kernel_launch(void* const* d_in, const int* in_sizes, int n_in,
                              void* d_out, int out_size)
{
    const float* x   = (const float*)d_in[0];
    const float* adj = (const float*)d_in[1];
    const float* W1  = (const float*)d_in[2];
    const float* b1  = (const float*)d_in[3];
    const float* W2  = (const float*)d_in[4];
    const float* b2  = (const float*)d_in[5];
    const float* g1  = (const float*)d_in[6];
    const float* be1 = (const float*)d_in[7];
    const float* m1  = (const float*)d_in[8];
    const float* v1  = (const float*)d_in[9];
    const float* g2  = (const float*)d_in[10];
    const float* be2 = (const float*)d_in[11];
    const float* m2  = (const float*)d_in[12];
    const float* v2  = (const float*)d_in[13];
    float* out = (float*)d_out;

    const int n_tok  = in_sizes[0] / HD;            // 32768
    const int blocks = n_tok / TOKENS_PER_BLK;      // 1024

    hand_gcn_kernel<<<blocks, THREADS>>>(
        x, adj, W1, b1, W2, b2, g1, be1, m1, v1, g2, be2, m2, v2, out);
}